// round 9
// baseline (speedup 1.0000x reference)
#include <cuda_runtime.h>
#include <cuda_bf16.h>
#include <cstdint>

#define N_POINTS 131072
#define N_NODES  2048
#define N_NPAIR  (N_NODES / 2)
#define N_GROUPS (N_NPAIR / 4)     // 256 groups of 4 node-pairs (8 nodes)
#define K_SEL    32
#define CAP      256               // max points buffered per node
#define KNN_BLOCKS  592            // 4 blocks/SM on 148 SMs, balanced ranges
#define KNN_THREADS 256

typedef unsigned long long u64;

// Scratch (no allocations allowed). Zero-initialized at load; select resets g_cnt.
__device__ int g_cnt[N_NODES];
__device__ int g_bucket[N_NODES * CAP];

// ---- packed f32x2 helpers (per-lane RN, bit-identical to scalar __f*_rn) ----
__device__ __forceinline__ u64 pk2(float lo, float hi) {
    u64 r; asm("mov.b64 %0, {%1, %2};" : "=l"(r) : "f"(lo), "f"(hi)); return r;
}
__device__ __forceinline__ void upk2(float& lo, float& hi, u64 v) {
    asm("mov.b64 {%0, %1}, %2;" : "=f"(lo), "=f"(hi) : "l"(v));
}
__device__ __forceinline__ u64 mul2(u64 a, u64 b) {
    u64 d; asm("mul.rn.f32x2 %0, %1, %2;" : "=l"(d) : "l"(a), "l"(b)); return d;
}
__device__ __forceinline__ u64 fma2(u64 a, u64 b, u64 c) {
    u64 d; asm("fma.rn.f32x2 %0, %1, %2, %3;" : "=l"(d) : "l"(a), "l"(b), "l"(c)); return d;
}
__device__ __forceinline__ u64 add2(u64 a, u64 b) {
    u64 d; asm("add.rn.f32x2 %0, %1, %2;" : "=l"(d) : "l"(a), "l"(b)); return d;
}

// Exact reference rounding chain (scalar), used for the recompute pass:
//   r1=RN(x*nx); r2=RN(y*ny+r1); r3=RN(z*nz+r2); r4=RN(-2*r3+pp); d2=RN(r4+nn)
__device__ __forceinline__ float d2_scalar(float x, float y, float z, float pp,
                                           float nx, float ny, float nz, float nn) {
    float r = __fmul_rn(x, nx);
    r = __fmaf_rn(y, ny, r);
    r = __fmaf_rn(z, nz, r);
    r = __fmaf_rn(-2.0f, r, pp);
    return __fadd_rn(r, nn);
}

// ---------------------------------------------------------------------------
// Kernel 1: 1-NN assign. ONE point per thread (doubles active warps/SMSP vs
// 2 pts/thread: 6.9 vs 3.46), 2 nodes per packed f32x2 lane, tournament
// argmin over groups of 4 node-pairs (8 nodes).
// Main-loop chain uses exact -2 pre-scaling of the point coordinates:
//   s1=RN((-2x)*nx) = -2*RN(x*nx)          (x2 scaling exact, RN-commutes)
//   s2=RN((-2y)*ny+s1); s3=RN((-2z)*nz+s2) = -2*r3
//   r4=RN(s3+pp) = RN(pp-2*r3); d2=RN(r4+nn)
// => bit-identical to the reference chain. Group winner -> exact recompute,
// first index among equal hits == jnp.argmin ascending tie-break.
// ---------------------------------------------------------------------------
extern __shared__ u64 s_nodes[];   // N_NPAIR * 4 u64 = 32 KB

__global__ void __launch_bounds__(KNN_THREADS, 4) knn_kernel(
    const float* __restrict__ pts,
    const float* __restrict__ nodes,
    float* __restrict__ out_d2,
    float* __restrict__ out_id)
{
    const int tid = threadIdx.x;

    // Fill node-pair cache (exact nn rounding as reference sum order).
    for (int m = tid; m < N_NPAIR; m += KNN_THREADS) {
        const float2* nf = (const float2*)nodes;
        float2 f0 = nf[3 * m + 0];   // nxA nyA
        float2 f1 = nf[3 * m + 1];   // nzA nxB
        float2 f2 = nf[3 * m + 2];   // nyB nzB
        float nxA = f0.x, nyA = f0.y, nzA = f1.x;
        float nxB = f1.y, nyB = f2.x, nzB = f2.y;
        float nnA = __fadd_rn(__fadd_rn(__fmul_rn(nxA, nxA), __fmul_rn(nyA, nyA)),
                              __fmul_rn(nzA, nzA));
        float nnB = __fadd_rn(__fadd_rn(__fmul_rn(nxB, nxB), __fmul_rn(nyB, nyB)),
                              __fmul_rn(nzB, nzB));
        s_nodes[4 * m + 0] = pk2(nxA, nxB);
        s_nodes[4 * m + 1] = pk2(nyA, nyB);
        s_nodes[4 * m + 2] = pk2(nzA, nzB);
        s_nodes[4 * m + 3] = pk2(nnA, nnB);
    }
    __syncthreads();

    // Balanced point ranges: ~221-222 points per block, one per thread.
    const int b     = blockIdx.x;
    const int start = (int)(((long long)b       * N_POINTS) / KNN_BLOCKS);
    const int end   = (int)(((long long)(b + 1) * N_POINTS) / KNN_BLOCKS);
    const int p     = start + tid;
    if (p >= end) return;

    const float x = pts[3 * p + 0];
    const float y = pts[3 * p + 1];
    const float z = pts[3 * p + 2];

    const float pp = __fadd_rn(__fadd_rn(__fmul_rn(x, x), __fmul_rn(y, y)),
                               __fmul_rn(z, z));

    // Exact -2 pre-scaled coordinates (exponent shift, no rounding).
    const float xm = -2.0f * x, ym = -2.0f * y, zm = -2.0f * z;

    const u64 X  = pk2(xm, xm);
    const u64 Y  = pk2(ym, ym);
    const u64 Z  = pk2(zm, zm);
    const u64 PP = pk2(pp, pp);

    float best = __int_as_float(0x7f800000);
    int   grp  = 0;

    const ulonglong2* sv = (const ulonglong2*)s_nodes;   // 2 x 16B per node-pair

#pragma unroll 1
    for (int g = 0; g < N_GROUPS; g++) {
        // Load 4 node-pairs (8 nodes) for this group.
        ulonglong2 a0 = sv[8 * g + 0], c0 = sv[8 * g + 1];
        ulonglong2 a1 = sv[8 * g + 2], c1 = sv[8 * g + 3];
        ulonglong2 a2 = sv[8 * g + 4], c2 = sv[8 * g + 5];
        ulonglong2 a3 = sv[8 * g + 6], c3 = sv[8 * g + 7];

        // 4 packed chains (8 nodes): mul2,fma2,fma2,add2,add2 each.
        u64 q0 = add2(add2(fma2(Z, c0.x, fma2(Y, a0.y, mul2(X, a0.x))), PP), c0.y);
        u64 q1 = add2(add2(fma2(Z, c1.x, fma2(Y, a1.y, mul2(X, a1.x))), PP), c1.y);
        u64 q2 = add2(add2(fma2(Z, c2.x, fma2(Y, a2.y, mul2(X, a2.x))), PP), c2.y);
        u64 q3 = add2(add2(fma2(Z, c3.x, fma2(Y, a3.y, mul2(X, a3.x))), PP), c3.y);

        float qa0, qb0, qa1, qb1, qa2, qb2, qa3, qb3;
        upk2(qa0, qb0, q0); upk2(qa1, qb1, q1);
        upk2(qa2, qb2, q2); upk2(qa3, qb3, q3);
        float t = fminf(fminf(fminf(qa0, qb0), fminf(qa1, qb1)),
                        fminf(fminf(qa2, qb2), fminf(qa3, qb3)));

        if (t < best) { best = t; grp = g; }   // strict '<': first group w/ min
    }

    // Recompute the winning group's 8 d2 bit-exactly (reference chain); first
    // index among equal hits (ascending j) == reference argmin tie-break.
    int idx = 0x7FFFFFFF;
#pragma unroll
    for (int t = 0; t < 4; t++) {
        int m = 4 * grp + t;
        ulonglong2 a = sv[2 * m + 0], c = sv[2 * m + 1];
        float nxA, nxB, nyA, nyB, nzA, nzB, nnA, nnB;
        upk2(nxA, nxB, a.x); upk2(nyA, nyB, a.y);
        upk2(nzA, nzB, c.x); upk2(nnA, nnB, c.y);
        float dA = d2_scalar(x, y, z, pp, nxA, nyA, nzA, nnA);
        float dB = d2_scalar(x, y, z, pp, nxB, nyB, nzB, nnB);
        if (dA == best) idx = min(idx, 2 * m);
        if (dB == best) idx = min(idx, 2 * m + 1);
    }

    out_d2[p] = best;
    out_id[p] = (float)idx;

    int pos = atomicAdd(&g_cnt[idx], 1);
    if (pos < CAP) g_bucket[idx * CAP + pos] = p;
}

// ---------------------------------------------------------------------------
// Kernel 2: per-node selection, one warp per node (proven 6.2-7.2us).
// ---------------------------------------------------------------------------
#define CE(a, b) { unsigned lo = min(a, b), hi = max(a, b); a = lo; b = hi; }

__global__ void __launch_bounds__(256) select_kernel(float* __restrict__ out_patch) {
    const int lane = threadIdx.x & 31;
    const int node = blockIdx.x * 8 + (threadIdx.x >> 5);
    const unsigned INF = 0x7FFFFFFFu;

    const int cnt = g_cnt[node];
    const int cl  = cnt < CAP ? cnt : CAP;
    if (lane == 0) g_cnt[node] = 0;      // reset for next graph replay

    const int base = node * CAP;
    unsigned e0 = (lane       < cl) ? (unsigned)g_bucket[base + lane      ] : INF;
    unsigned e1 = (lane + 32  < cl) ? (unsigned)g_bucket[base + lane + 32 ] : INF;
    unsigned e2 = (lane + 64  < cl) ? (unsigned)g_bucket[base + lane + 64 ] : INF;
    unsigned e3 = (lane + 96  < cl) ? (unsigned)g_bucket[base + lane + 96 ] : INF;
    unsigned e4 = (lane + 128 < cl) ? (unsigned)g_bucket[base + lane + 128] : INF;
    unsigned e5 = (lane + 160 < cl) ? (unsigned)g_bucket[base + lane + 160] : INF;
    unsigned e6 = (lane + 192 < cl) ? (unsigned)g_bucket[base + lane + 192] : INF;
    unsigned e7 = (lane + 224 < cl) ? (unsigned)g_bucket[base + lane + 224] : INF;

    // Batcher odd-even merge sort network for 8 (19 compare-exchanges).
    CE(e0, e1) CE(e2, e3) CE(e4, e5) CE(e6, e7)
    CE(e0, e2) CE(e1, e3) CE(e4, e6) CE(e5, e7)
    CE(e1, e2) CE(e5, e6)
    CE(e0, e4) CE(e1, e5) CE(e2, e6) CE(e3, e7)
    CE(e2, e4) CE(e3, e5)
    CE(e1, e2) CE(e3, e4) CE(e5, e6)

    unsigned keep = INF;
#pragma unroll
    for (int t = 0; t < K_SEL; t++) {
        unsigned m = __reduce_min_sync(0xFFFFFFFFu, e0);
        if (lane == t) keep = m;
        bool hit = (e0 == m);            // unique indices: at most one real hit
        e0 = hit ? e1 : e0;
        e1 = hit ? e2 : e1;
        e2 = hit ? e3 : e2;
        e3 = hit ? e4 : e3;
        e4 = hit ? e5 : e4;
        e5 = hit ? e6 : e5;
        e6 = hit ? e7 : e6;
        e7 = hit ? INF : e7;
    }

    out_patch[node * K_SEL + lane] = (lane < cl) ? (float)keep : 0.0f;
}

// ---------------------------------------------------------------------------
// Launch: outputs concatenated as [min_d2 | pcd_id | patch], all float32.
// ---------------------------------------------------------------------------
extern "C" void kernel_launch(void* const* d_in, const int* in_sizes, int n_in,
                              void* d_out, int out_size)
{
    const float* pts   = (const float*)d_in[0];   // [131072, 3]
    const float* nodes = (const float*)d_in[1];   // [2048, 3]

    float* out       = (float*)d_out;
    float* out_d2    = out;                        // 131072
    float* out_id    = out + N_POINTS;             // 131072
    float* out_patch = out + 2 * N_POINTS;         // 2048*32

    const size_t smem_bytes = (size_t)N_NPAIR * 4 * sizeof(u64);  // 32 KB
    (void)cudaFuncSetAttribute(knn_kernel,
                               cudaFuncAttributeMaxDynamicSharedMemorySize,
                               (int)smem_bytes);

    knn_kernel<<<KNN_BLOCKS, KNN_THREADS, smem_bytes>>>(pts, nodes, out_d2, out_id);
    select_kernel<<<N_NODES / 8, 256>>>(out_patch);
}

// round 12
// speedup vs baseline: 1.0797x; 1.0797x over previous
#include <cuda_runtime.h>
#include <cuda_bf16.h>
#include <cstdint>

#define N_POINTS 131072
#define N_PAIRS  (N_POINTS / 2)
#define N_NODES  2048
#define N_NPAIR  (N_NODES / 2)
#define N_GROUPS (N_NPAIR / 4)     // 256 groups of 4 node-pairs (8 nodes)
#define K_SEL    32
#define CAP      256               // max points buffered per node
#define KNN_BLOCKS  296            // 2 blocks/SM on 148 SMs, balanced ranges
#define KNN_THREADS 256

typedef unsigned long long u64;

// Scratch (no allocations allowed). Zero-initialized at load; select resets g_cnt.
__device__ int g_cnt[N_NODES];
__device__ int g_bucket[N_NODES * CAP];

// ---- packed f32x2 helpers (per-lane RN, bit-identical to scalar __f*_rn) ----
__device__ __forceinline__ u64 pk2(float lo, float hi) {
    u64 r; asm("mov.b64 %0, {%1, %2};" : "=l"(r) : "f"(lo), "f"(hi)); return r;
}
__device__ __forceinline__ void upk2(float& lo, float& hi, u64 v) {
    asm("mov.b64 {%0, %1}, %2;" : "=f"(lo), "=f"(hi) : "l"(v));
}
__device__ __forceinline__ u64 mul2(u64 a, u64 b) {
    u64 d; asm("mul.rn.f32x2 %0, %1, %2;" : "=l"(d) : "l"(a), "l"(b)); return d;
}
__device__ __forceinline__ u64 fma2(u64 a, u64 b, u64 c) {
    u64 d; asm("fma.rn.f32x2 %0, %1, %2, %3;" : "=l"(d) : "l"(a), "l"(b), "l"(c)); return d;
}
__device__ __forceinline__ u64 add2(u64 a, u64 b) {
    u64 d; asm("add.rn.f32x2 %0, %1, %2;" : "=l"(d) : "l"(a), "l"(b)); return d;
}

// Exact reference rounding chain (scalar), used for the recompute pass:
//   r1=RN(x*nx); r2=RN(y*ny+r1); r3=RN(z*nz+r2); r4=RN(-2*r3+pp); d2=RN(r4+nn)
__device__ __forceinline__ float d2_scalar(float x, float y, float z, float pp,
                                           float nx, float ny, float nz, float nn) {
    float r = __fmul_rn(x, nx);
    r = __fmaf_rn(y, ny, r);
    r = __fmaf_rn(z, nz, r);
    r = __fmaf_rn(-2.0f, r, pp);
    return __fadd_rn(r, nn);
}

// ---------------------------------------------------------------------------
// Kernel 1: 1-NN assign. 2 points/thread, 2 nodes per packed f32x2 lane,
// tournament argmin over groups of 4 node-pairs (8 nodes).
// Main-loop chain uses exact -2 pre-scaling of the point coordinates:
//   s1=RN((-2x)*nx) = -2*RN(x*nx)          (x2 scaling exact, RN-commutes)
//   s2=RN((-2y)*ny+s1); s3=RN((-2z)*nz+s2) = -2*r3
//   r4=RN(s3+pp) = RN(pp-2*r3); d2=RN(r4+nn)
// => bit-identical to the reference chain. Group winner -> exact recompute,
// first index among equal hits == jnp.argmin ascending tie-break.
// ---------------------------------------------------------------------------
extern __shared__ u64 s_nodes[];   // N_NPAIR * 4 u64 = 32 KB

__global__ void __launch_bounds__(KNN_THREADS, 2) knn_kernel(
    const float* __restrict__ pts,
    const float* __restrict__ nodes,
    float* __restrict__ out_d2,
    float* __restrict__ out_id)
{
    const int tid = threadIdx.x;

    // Fill node-pair cache (exact nn rounding as reference sum order).
    for (int m = tid; m < N_NPAIR; m += KNN_THREADS) {
        const float2* nf = (const float2*)nodes;
        float2 f0 = nf[3 * m + 0];   // nxA nyA
        float2 f1 = nf[3 * m + 1];   // nzA nxB
        float2 f2 = nf[3 * m + 2];   // nyB nzB
        float nxA = f0.x, nyA = f0.y, nzA = f1.x;
        float nxB = f1.y, nyB = f2.x, nzB = f2.y;
        float nnA = __fadd_rn(__fadd_rn(__fmul_rn(nxA, nxA), __fmul_rn(nyA, nyA)),
                              __fmul_rn(nzA, nzA));
        float nnB = __fadd_rn(__fadd_rn(__fmul_rn(nxB, nxB), __fmul_rn(nyB, nyB)),
                              __fmul_rn(nzB, nzB));
        s_nodes[4 * m + 0] = pk2(nxA, nxB);
        s_nodes[4 * m + 1] = pk2(nyA, nyB);
        s_nodes[4 * m + 2] = pk2(nzA, nzB);
        s_nodes[4 * m + 3] = pk2(nnA, nnB);
    }
    __syncthreads();

    // Balanced point-pair ranges: ~221-222 pairs per block, one per thread.
    const int b     = blockIdx.x;
    const int start = (int)(((long long)b       * N_PAIRS) / KNN_BLOCKS);
    const int end   = (int)(((long long)(b + 1) * N_PAIRS) / KNN_BLOCKS);
    const int p     = start + tid;
    if (p >= end) return;

    // Two consecutive points (coalesced float2 loads).
    const float2* pf = (const float2*)pts;
    float2 f0 = pf[3 * p + 0];
    float2 f1 = pf[3 * p + 1];
    float2 f2 = pf[3 * p + 2];
    const float x0 = f0.x, y0 = f0.y, z0 = f1.x;
    const float x1 = f1.y, y1 = f2.x, z1 = f2.y;

    const float pp0 = __fadd_rn(__fadd_rn(__fmul_rn(x0, x0), __fmul_rn(y0, y0)),
                                __fmul_rn(z0, z0));
    const float pp1 = __fadd_rn(__fadd_rn(__fmul_rn(x1, x1), __fmul_rn(y1, y1)),
                                __fmul_rn(z1, z1));

    // Exact -2 pre-scaled coordinates (exponent shift, no rounding).
    const float x0m = -2.0f * x0, y0m = -2.0f * y0, z0m = -2.0f * z0;
    const float x1m = -2.0f * x1, y1m = -2.0f * y1, z1m = -2.0f * z1;

    const u64 X0 = pk2(x0m, x0m), Y0 = pk2(y0m, y0m), Z0 = pk2(z0m, z0m), PP0 = pk2(pp0, pp0);
    const u64 X1 = pk2(x1m, x1m), Y1 = pk2(y1m, y1m), Z1 = pk2(z1m, z1m), PP1 = pk2(pp1, pp1);

    float best0 = __int_as_float(0x7f800000);
    float best1 = __int_as_float(0x7f800000);
    int   grp0 = 0, grp1 = 0;

    const ulonglong2* sv = (const ulonglong2*)s_nodes;   // 2 x 16B per node-pair

#pragma unroll 4
    for (int g = 0; g < N_GROUPS; g++) {
        // Load 4 node-pairs (8 nodes) for this group.
        ulonglong2 a0 = sv[8 * g + 0], c0 = sv[8 * g + 1];
        ulonglong2 a1 = sv[8 * g + 2], c1 = sv[8 * g + 3];
        ulonglong2 a2 = sv[8 * g + 4], c2 = sv[8 * g + 5];
        ulonglong2 a3 = sv[8 * g + 6], c3 = sv[8 * g + 7];

        // Point 0 vs 8 nodes (4 packed chains): mul2,fma2,fma2,add2,add2.
        u64 q0 = add2(add2(fma2(Z0, c0.x, fma2(Y0, a0.y, mul2(X0, a0.x))), PP0), c0.y);
        u64 q1 = add2(add2(fma2(Z0, c1.x, fma2(Y0, a1.y, mul2(X0, a1.x))), PP0), c1.y);
        u64 q2 = add2(add2(fma2(Z0, c2.x, fma2(Y0, a2.y, mul2(X0, a2.x))), PP0), c2.y);
        u64 q3 = add2(add2(fma2(Z0, c3.x, fma2(Y0, a3.y, mul2(X0, a3.x))), PP0), c3.y);
        // Point 1 vs same 8 nodes.
        u64 s0 = add2(add2(fma2(Z1, c0.x, fma2(Y1, a0.y, mul2(X1, a0.x))), PP1), c0.y);
        u64 s1 = add2(add2(fma2(Z1, c1.x, fma2(Y1, a1.y, mul2(X1, a1.x))), PP1), c1.y);
        u64 s2 = add2(add2(fma2(Z1, c2.x, fma2(Y1, a2.y, mul2(X1, a2.x))), PP1), c2.y);
        u64 s3 = add2(add2(fma2(Z1, c3.x, fma2(Y1, a3.y, mul2(X1, a3.x))), PP1), c3.y);

        float qa0, qb0, qa1, qb1, qa2, qb2, qa3, qb3;
        upk2(qa0, qb0, q0); upk2(qa1, qb1, q1);
        upk2(qa2, qb2, q2); upk2(qa3, qb3, q3);
        float t0 = fminf(fminf(fminf(qa0, qb0), fminf(qa1, qb1)),
                         fminf(fminf(qa2, qb2), fminf(qa3, qb3)));

        float sa0, sb0, sa1, sb1, sa2, sb2, sa3, sb3;
        upk2(sa0, sb0, s0); upk2(sa1, sb1, s1);
        upk2(sa2, sb2, s2); upk2(sa3, sb3, s3);
        float t1 = fminf(fminf(fminf(sa0, sb0), fminf(sa1, sb1)),
                         fminf(fminf(sa2, sb2), fminf(sa3, sb3)));

        if (t0 < best0) { best0 = t0; grp0 = g; }   // strict '<': first group w/ min
        if (t1 < best1) { best1 = t1; grp1 = g; }
    }

    // Recompute the winning group's 8 d2 bit-exactly (reference chain); first
    // index among equal hits (ascending j) == reference argmin tie-break.
    int i0 = 0x7FFFFFFF, i1 = 0x7FFFFFFF;
#pragma unroll
    for (int t = 0; t < 4; t++) {
        {
            int m = 4 * grp0 + t;
            ulonglong2 a = sv[2 * m + 0], c = sv[2 * m + 1];
            float nxA, nxB, nyA, nyB, nzA, nzB, nnA, nnB;
            upk2(nxA, nxB, a.x); upk2(nyA, nyB, a.y);
            upk2(nzA, nzB, c.x); upk2(nnA, nnB, c.y);
            float dA = d2_scalar(x0, y0, z0, pp0, nxA, nyA, nzA, nnA);
            float dB = d2_scalar(x0, y0, z0, pp0, nxB, nyB, nzB, nnB);
            if (dA == best0) i0 = min(i0, 2 * m);
            if (dB == best0) i0 = min(i0, 2 * m + 1);
        }
        {
            int m = 4 * grp1 + t;
            ulonglong2 a = sv[2 * m + 0], c = sv[2 * m + 1];
            float nxA, nxB, nyA, nyB, nzA, nzB, nnA, nnB;
            upk2(nxA, nxB, a.x); upk2(nyA, nyB, a.y);
            upk2(nzA, nzB, c.x); upk2(nnA, nnB, c.y);
            float dA = d2_scalar(x1, y1, z1, pp1, nxA, nyA, nzA, nnA);
            float dB = d2_scalar(x1, y1, z1, pp1, nxB, nyB, nzB, nnB);
            if (dA == best1) i1 = min(i1, 2 * m);
            if (dB == best1) i1 = min(i1, 2 * m + 1);
        }
    }

    const int pt0 = 2 * p, pt1 = 2 * p + 1;
    out_d2[pt0] = best0;
    out_d2[pt1] = best1;
    out_id[pt0] = (float)i0;
    out_id[pt1] = (float)i1;

    int pos0 = atomicAdd(&g_cnt[i0], 1);
    if (pos0 < CAP) g_bucket[i0 * CAP + pos0] = pt0;
    int pos1 = atomicAdd(&g_cnt[i1], 1);
    if (pos1 < CAP) g_bucket[i1 * CAP + pos1] = pt1;
}

// ---------------------------------------------------------------------------
// Kernel 2: per-node selection, one warp per node (proven 6.2-7.2us).
// ---------------------------------------------------------------------------
#define CE(a, b) { unsigned lo = min(a, b), hi = max(a, b); a = lo; b = hi; }

__global__ void __launch_bounds__(256) select_kernel(float* __restrict__ out_patch) {
    const int lane = threadIdx.x & 31;
    const int node = blockIdx.x * 8 + (threadIdx.x >> 5);
    const unsigned INF = 0x7FFFFFFFu;

    const int cnt = g_cnt[node];
    const int cl  = cnt < CAP ? cnt : CAP;
    if (lane == 0) g_cnt[node] = 0;      // reset for next graph replay

    const int base = node * CAP;
    unsigned e0 = (lane       < cl) ? (unsigned)g_bucket[base + lane      ] : INF;
    unsigned e1 = (lane + 32  < cl) ? (unsigned)g_bucket[base + lane + 32 ] : INF;
    unsigned e2 = (lane + 64  < cl) ? (unsigned)g_bucket[base + lane + 64 ] : INF;
    unsigned e3 = (lane + 96  < cl) ? (unsigned)g_bucket[base + lane + 96 ] : INF;
    unsigned e4 = (lane + 128 < cl) ? (unsigned)g_bucket[base + lane + 128] : INF;
    unsigned e5 = (lane + 160 < cl) ? (unsigned)g_bucket[base + lane + 160] : INF;
    unsigned e6 = (lane + 192 < cl) ? (unsigned)g_bucket[base + lane + 192] : INF;
    unsigned e7 = (lane + 224 < cl) ? (unsigned)g_bucket[base + lane + 224] : INF;

    // Batcher odd-even merge sort network for 8 (19 compare-exchanges).
    CE(e0, e1) CE(e2, e3) CE(e4, e5) CE(e6, e7)
    CE(e0, e2) CE(e1, e3) CE(e4, e6) CE(e5, e7)
    CE(e1, e2) CE(e5, e6)
    CE(e0, e4) CE(e1, e5) CE(e2, e6) CE(e3, e7)
    CE(e2, e4) CE(e3, e5)
    CE(e1, e2) CE(e3, e4) CE(e5, e6)

    unsigned keep = INF;
#pragma unroll
    for (int t = 0; t < K_SEL; t++) {
        unsigned m = __reduce_min_sync(0xFFFFFFFFu, e0);
        if (lane == t) keep = m;
        bool hit = (e0 == m);            // unique indices: at most one real hit
        e0 = hit ? e1 : e0;
        e1 = hit ? e2 : e1;
        e2 = hit ? e3 : e2;
        e3 = hit ? e4 : e3;
        e4 = hit ? e5 : e4;
        e5 = hit ? e6 : e5;
        e6 = hit ? e7 : e6;
        e7 = hit ? INF : e7;
    }

    out_patch[node * K_SEL + lane] = (lane < cl) ? (float)keep : 0.0f;
}

// ---------------------------------------------------------------------------
// Launch: outputs concatenated as [min_d2 | pcd_id | patch], all float32.
// ---------------------------------------------------------------------------
extern "C" void kernel_launch(void* const* d_in, const int* in_sizes, int n_in,
                              void* d_out, int out_size)
{
    const float* pts   = (const float*)d_in[0];   // [131072, 3]
    const float* nodes = (const float*)d_in[1];   // [2048, 3]

    float* out       = (float*)d_out;
    float* out_d2    = out;                        // 131072
    float* out_id    = out + N_POINTS;             // 131072
    float* out_patch = out + 2 * N_POINTS;         // 2048*32

    const size_t smem_bytes = (size_t)N_NPAIR * 4 * sizeof(u64);  // 32 KB
    (void)cudaFuncSetAttribute(knn_kernel,
                               cudaFuncAttributeMaxDynamicSharedMemorySize,
                               (int)smem_bytes);

    knn_kernel<<<KNN_BLOCKS, KNN_THREADS, smem_bytes>>>(pts, nodes, out_d2, out_id);
    select_kernel<<<N_NODES / 8, 256>>>(out_patch);
}